// round 1
// baseline (speedup 1.0000x reference)
#include <cuda_runtime.h>
#include <math.h>
#include <stdint.h>

// ---------------- problem constants ----------------
#define NCTA  128
#define TPB   512
#define HID   1536
#define INSZ  32
#define NOUT  10
#define STOT  2048          // T * INPUT_SIZE = 64 * 32
#define UPC   (HID / NCTA)  // 12 hidden units per CTA
#define RPC   (4 * UPC)     // 48 gate rows per CTA (i,f,g,o)
#define NWARP (TPB / 32)    // 16
#define RPW   (RPC / NWARP) // 3 rows per warp
#define HV4   (HID / 4)     // 384 float4 per hidden vector
#define ITER  (HV4 / 32)    // 12 inner iterations per dot

// ---------------- persistent device state ----------------
__device__ float    g_h0[2][HID];
__device__ float    g_h1[2][HID];
__device__ float    g_part[NCTA][NOUT];
__device__ unsigned g_bar_count = 0;
__device__ unsigned g_bar_gen   = 0;

// ---------------- grid barrier (persistent-kernel idiom) ----------------
__device__ __forceinline__ void grid_barrier() {
    __syncthreads();
    if (threadIdx.x == 0) {
        __threadfence();
        unsigned g = *((volatile unsigned*)&g_bar_gen);
        unsigned arrived = atomicAdd(&g_bar_count, 1u);
        if (arrived == NCTA - 1) {
            atomicExch(&g_bar_count, 0u);
            __threadfence();
            atomicExch(&g_bar_gen, g + 1u);
        } else {
            while (*((volatile unsigned*)&g_bar_gen) == g) { }
        }
        __threadfence();
    }
    __syncthreads();
}

// ---------------- JAX threefry2x32 (20 rounds) ----------------
__device__ __forceinline__ void tf_round(uint32_t& x0, uint32_t& x1, int r) {
    x0 += x1;
    x1 = (x1 << r) | (x1 >> (32 - r));
    x1 ^= x0;
}

__device__ __forceinline__ uint2 threefry2x32(uint32_t k0, uint32_t k1,
                                              uint32_t x0, uint32_t x1) {
    uint32_t ks2 = k0 ^ k1 ^ 0x1BD11BDAu;
    x0 += k0; x1 += k1;
    tf_round(x0,x1,13); tf_round(x0,x1,15); tf_round(x0,x1,26); tf_round(x0,x1,6);
    x0 += k1; x1 += ks2 + 1u;
    tf_round(x0,x1,17); tf_round(x0,x1,29); tf_round(x0,x1,16); tf_round(x0,x1,24);
    x0 += ks2; x1 += k0 + 2u;
    tf_round(x0,x1,13); tf_round(x0,x1,15); tf_round(x0,x1,26); tf_round(x0,x1,6);
    x0 += k0; x1 += k1 + 3u;
    tf_round(x0,x1,17); tf_round(x0,x1,29); tf_round(x0,x1,16); tf_round(x0,x1,24);
    x0 += k1; x1 += ks2 + 4u;
    tf_round(x0,x1,13); tf_round(x0,x1,15); tf_round(x0,x1,26); tf_round(x0,x1,6);
    x0 += ks2; x1 += k0 + 5u;
    return make_uint2(x0, x1);
}

__device__ __forceinline__ float dot4(float4 a, float4 b, float acc) {
    acc = fmaf(a.x, b.x, acc);
    acc = fmaf(a.y, b.y, acc);
    acc = fmaf(a.z, b.z, acc);
    acc = fmaf(a.w, b.w, acc);
    return acc;
}

__device__ __forceinline__ float sigf(float x) {
    return 1.0f / (1.0f + expf(-x));
}

// ---------------- the persistent kernel ----------------
__global__ void __launch_bounds__(TPB, 1)
lstm_autoreg_kernel(const float* __restrict__ inputs,
                    const float* __restrict__ h_init,
                    const float* __restrict__ c_init,
                    const float* __restrict__ W_ih0,
                    const float* __restrict__ W_hh0,
                    const float* __restrict__ b_ih0,
                    const float* __restrict__ b_hh0,
                    const float* __restrict__ W_ih1,
                    const float* __restrict__ W_hh1,
                    const float* __restrict__ b_ih1,
                    const float* __restrict__ b_hh1,
                    const float* __restrict__ W_lin,
                    const float* __restrict__ b_lin,
                    const float* __restrict__ lookup,
                    float* __restrict__ out)
{
    __shared__ float s_hA[HID];             // staged hidden vector A
    __shared__ float s_hB[HID];             // staged hidden vector B
    __shared__ float s_Wih0[RPC][INSZ];     // this CTA's W_ih0 rows (local copy)
    __shared__ float s_bias0[RPC];          // b_ih0 + b_hh0 (local rows)
    __shared__ float s_bias1[RPC];          // b_ih1 + b_hh1 (local rows)
    __shared__ float s_gih0[RPC];           // incremental x @ W_ih0^T + bias0
    __shared__ float s_gates[RPC];          // gate scratch
    __shared__ float s_c0[UPC], s_c1[UPC];  // cell states (local units)
    __shared__ float s_h1loc[UPC];          // this CTA's new h1 units
    __shared__ float s_x[INSZ];             // current augmented input
    __shared__ float s_Wlin[NOUT][UPC];     // W_lin columns for local units
    __shared__ float s_lookup[NOUT];
    __shared__ float s_blin[NOUT];
    __shared__ float s_logits[NOUT];
    __shared__ float s_scale;

    const int tid  = threadIdx.x;
    const int cta  = blockIdx.x;
    const int u0   = cta * UPC;
    const int warp = tid >> 5;
    const int lane = tid & 31;
    const float neginf = __int_as_float(0xff800000);

    // ---------------- one-time init ----------------
    for (int r = tid; r < RPC; r += TPB) {
        int t = r / UPC, ul = r - t * UPC;
        int grow = t * HID + u0 + ul;
        s_bias0[r] = b_ih0[grow] + b_hh0[grow];
        s_bias1[r] = b_ih1[grow] + b_hh1[grow];
    }
    for (int idx = tid; idx < RPC * INSZ; idx += TPB) {
        int r = idx >> 5, k = idx & 31;
        int t = r / UPC, ul = r - t * UPC;
        s_Wih0[r][k] = W_ih0[(t * HID + u0 + ul) * INSZ + k];
    }
    for (int idx = tid; idx < NOUT * UPC; idx += TPB) {
        int o = idx / UPC, ul = idx - o * UPC;
        s_Wlin[o][ul] = W_lin[o * HID + u0 + ul];
    }
    if (tid < NOUT) { s_lookup[tid] = lookup[tid]; s_blin[tid] = b_lin[tid]; }
    if (tid < UPC) {
        s_c0[tid] = c_init[u0 + tid];
        s_c1[tid] = c_init[HID + u0 + tid];
        g_h0[0][u0 + tid] = h_init[u0 + tid];
        g_h1[0][u0 + tid] = h_init[HID + u0 + tid];
    }
    grid_barrier();

    int p = 0;
    for (int s = 0; s < STOT; ++s) {
        const int i_t = s >> 5;
        const int j   = s & 31;
        __syncthreads();   // protect s_x / s_gih0 from last step's tail writes

        // fresh input at start of each timestep: rebuild x and its gate contribution
        if (j == 0) {
            if (tid < INSZ) s_x[tid] = inputs[i_t * INSZ + tid];
            __syncthreads();
            for (int r = tid; r < RPC; r += TPB) {
                float acc = s_bias0[r];
                #pragma unroll
                for (int k = 0; k < INSZ; ++k) acc = fmaf(s_x[k], s_Wih0[r][k], acc);
                s_gih0[r] = acc;
            }
        }

        // ---- phase A: layer-0 cell ----
        {
            const float4* src = (const float4*)(&g_h0[p][0]);
            float4* dst = (float4*)s_hA;
            for (int q = tid; q < HV4; q += TPB) dst[q] = src[q];
        }
        __syncthreads();
        {
            const int lr0 = warp * RPW;
            int r;
            r = lr0;     const float4* wA = (const float4*)(W_hh0 + (size_t)((r / UPC) * HID + u0 + (r % UPC)) * HID);
            r = lr0 + 1; const float4* wB = (const float4*)(W_hh0 + (size_t)((r / UPC) * HID + u0 + (r % UPC)) * HID);
            r = lr0 + 2; const float4* wC = (const float4*)(W_hh0 + (size_t)((r / UPC) * HID + u0 + (r % UPC)) * HID);
            const float4* hv = (const float4*)s_hA;
            float a0 = 0.f, a1 = 0.f, a2 = 0.f;
            #pragma unroll 4
            for (int it = 0; it < ITER; ++it) {
                int idx = lane + (it << 5);
                float4 h = hv[idx];
                a0 = dot4(wA[idx], h, a0);
                a1 = dot4(wB[idx], h, a1);
                a2 = dot4(wC[idx], h, a2);
            }
            #pragma unroll
            for (int off = 16; off; off >>= 1) {
                a0 += __shfl_xor_sync(0xffffffffu, a0, off);
                a1 += __shfl_xor_sync(0xffffffffu, a1, off);
                a2 += __shfl_xor_sync(0xffffffffu, a2, off);
            }
            if (lane == 0) {
                s_gates[lr0]     = s_gih0[lr0]     + a0;
                s_gates[lr0 + 1] = s_gih0[lr0 + 1] + a1;
                s_gates[lr0 + 2] = s_gih0[lr0 + 2] + a2;
            }
        }
        __syncthreads();
        if (tid < UPC) {
            float gi = s_gates[tid];
            float gf = s_gates[UPC + tid];
            float gg = s_gates[2 * UPC + tid];
            float go = s_gates[3 * UPC + tid];
            float c2 = sigf(gf) * s_c0[tid] + sigf(gi) * tanhf(gg);
            float h2 = sigf(go) * tanhf(c2);
            s_c0[tid] = c2;
            g_h0[p ^ 1][u0 + tid] = h2;
        }
        grid_barrier();

        // ---- phase B: layer-1 cell + partial logits ----
        {
            const float4* srcA = (const float4*)(&g_h0[p ^ 1][0]);
            const float4* srcB = (const float4*)(&g_h1[p][0]);
            float4* dA = (float4*)s_hA;
            float4* dB = (float4*)s_hB;
            for (int q = tid; q < HV4; q += TPB) { dA[q] = srcA[q]; dB[q] = srcB[q]; }
        }
        __syncthreads();
        {
            const int lr0 = warp * RPW;
            int r;
            r = lr0;     size_t roA = (size_t)((r / UPC) * HID + u0 + (r % UPC)) * HID;
            r = lr0 + 1; size_t roB = (size_t)((r / UPC) * HID + u0 + (r % UPC)) * HID;
            r = lr0 + 2; size_t roC = (size_t)((r / UPC) * HID + u0 + (r % UPC)) * HID;
            const float4* wiA = (const float4*)(W_ih1 + roA);
            const float4* wiB = (const float4*)(W_ih1 + roB);
            const float4* wiC = (const float4*)(W_ih1 + roC);
            const float4* whA = (const float4*)(W_hh1 + roA);
            const float4* whB = (const float4*)(W_hh1 + roB);
            const float4* whC = (const float4*)(W_hh1 + roC);
            const float4* h0v = (const float4*)s_hA;
            const float4* h1v = (const float4*)s_hB;
            float a0 = 0.f, a1 = 0.f, a2 = 0.f;
            #pragma unroll 2
            for (int it = 0; it < ITER; ++it) {
                int idx = lane + (it << 5);
                float4 ha = h0v[idx];
                float4 hb = h1v[idx];
                a0 = dot4(wiA[idx], ha, a0); a0 = dot4(whA[idx], hb, a0);
                a1 = dot4(wiB[idx], ha, a1); a1 = dot4(whB[idx], hb, a1);
                a2 = dot4(wiC[idx], ha, a2); a2 = dot4(whC[idx], hb, a2);
            }
            #pragma unroll
            for (int off = 16; off; off >>= 1) {
                a0 += __shfl_xor_sync(0xffffffffu, a0, off);
                a1 += __shfl_xor_sync(0xffffffffu, a1, off);
                a2 += __shfl_xor_sync(0xffffffffu, a2, off);
            }
            if (lane == 0) {
                s_gates[lr0]     = s_bias1[lr0]     + a0;
                s_gates[lr0 + 1] = s_bias1[lr0 + 1] + a1;
                s_gates[lr0 + 2] = s_bias1[lr0 + 2] + a2;
            }
        }
        __syncthreads();
        if (tid < UPC) {
            float gi = s_gates[tid];
            float gf = s_gates[UPC + tid];
            float gg = s_gates[2 * UPC + tid];
            float go = s_gates[3 * UPC + tid];
            float c2 = sigf(gf) * s_c1[tid] + sigf(gi) * tanhf(gg);
            float h2 = sigf(go) * tanhf(c2);
            s_c1[tid] = c2;
            s_h1loc[tid] = h2;
            g_h1[p ^ 1][u0 + tid] = h2;
        }
        __syncthreads();
        if (tid < NOUT) {
            float acc = 0.f;
            #pragma unroll
            for (int ul = 0; ul < UPC; ++ul) acc = fmaf(s_h1loc[ul], s_Wlin[tid][ul], acc);
            g_part[cta][tid] = acc;
        }
        grid_barrier();

        // ---- phase C: deterministic logits sum + sampling (redundant per CTA) ----
        if (tid < NOUT) {
            float l = s_blin[tid];
            for (int c = 0; c < NCTA; ++c) l += g_part[c][tid];
            s_logits[tid] = l;
        }
        __syncthreads();
        if (warp == 0) {
            float logit = (lane < NOUT) ? s_logits[lane] : neginf;
            // JAX partitionable threefry: key_s = tf((0,42),(0,s)); bits_c = o0^o1 of tf(key,(0,c))
            uint2 key = threefry2x32(0u, 42u, 0u, (uint32_t)s);
            float v = neginf;
            if (lane < NOUT) {
                uint2 bb = threefry2x32(key.x, key.y, 0u, (uint32_t)lane);
                uint32_t bits = bb.x ^ bb.y;
                float f = __uint_as_float((bits >> 9) | 0x3F800000u) - 1.0f;
                float u = f + 1.17549435e-38f;
                u = fmaxf(u, 1.17549435e-38f);
                float gum = -logf(-logf(u));
                v = logit + gum;
            }
            int aidx = lane;
            #pragma unroll
            for (int off = 16; off; off >>= 1) {
                float ov = __shfl_xor_sync(0xffffffffu, v, off);
                int   oi = __shfl_xor_sync(0xffffffffu, aidx, off);
                if (ov > v || (ov == v && oi < aidx)) { v = ov; aidx = oi; }
            }
            float m = logit;
            #pragma unroll
            for (int off = 16; off; off >>= 1)
                m = fmaxf(m, __shfl_xor_sync(0xffffffffu, m, off));
            float e = (lane < NOUT) ? expf(logit - m) : 0.f;
            float sum = e;
            #pragma unroll
            for (int off = 16; off; off >>= 1)
                sum += __shfl_xor_sync(0xffffffffu, sum, off);
            if (lane == 0) s_scale = (j == 0) ? 1.0f : s_lookup[aidx];
            if (cta == 0) {
                if (lane == 0) out[s] = (float)aidx;
                if (lane < NOUT) out[STOT + s * NOUT + lane] = e / sum;
            }
        }
        __syncthreads();

        // ---- rank-1 update of x and its cached gate contribution ----
        if (j != 0) {
            float sc = s_scale;
            float xj = s_x[j];
            __syncthreads();
            if (tid < RPC) s_gih0[tid] = fmaf((sc - 1.0f) * xj, s_Wih0[tid][j], s_gih0[tid]);
            if (tid == 0)  s_x[j] = xj * sc;
        }
        p ^= 1;
    }
}

extern "C" void kernel_launch(void* const* d_in, const int* in_sizes, int n_in,
                              void* d_out, int out_size) {
    (void)in_sizes; (void)n_in; (void)out_size;
    lstm_autoreg_kernel<<<NCTA, TPB>>>(
        (const float*)d_in[0],   // inputs
        (const float*)d_in[1],   // h_init
        (const float*)d_in[2],   // c_init
        (const float*)d_in[3],   // W_ih0
        (const float*)d_in[4],   // W_hh0
        (const float*)d_in[5],   // b_ih0
        (const float*)d_in[6],   // b_hh0
        (const float*)d_in[7],   // W_ih1
        (const float*)d_in[8],   // W_hh1
        (const float*)d_in[9],   // b_ih1
        (const float*)d_in[10],  // b_hh1
        (const float*)d_in[11],  // W_lin
        (const float*)d_in[12],  // b_lin
        (const float*)d_in[13],  // lookup
        (float*)d_out);
}

// round 2
// speedup vs baseline: 1.3813x; 1.3813x over previous
#include <cuda_runtime.h>
#include <math.h>
#include <stdint.h>

// ---------------- problem constants ----------------
#define NCTA  128
#define TPB   768
#define NWARP (TPB / 32)     // 24
#define HID   1536
#define INSZ  32
#define NOUT  10
#define STOT  2048           // T * INPUT_SIZE
#define UPC   (HID / NCTA)   // 12 hidden units per CTA
#define RPC   (4 * UPC)      // 48 gate rows per CTA
#define RPW   (RPC / NWARP)  // 2 rows per warp
#define HV4   (HID / 4)      // 384 float4 per hidden vector
#define NWEL  (4 * HID * HID) // elements per big matrix = 9437184

// ---------------- persistent device state ----------------
// compressed weights: hi = fp32 bits[31:16], mid = bits[15:8] (RN at conversion)
__device__ unsigned short g_hi_hh0[NWEL];
__device__ unsigned short g_hi_ih1[NWEL];
__device__ unsigned short g_hi_hh1[NWEL];
__device__ unsigned char  g_mi_hh0[NWEL];
__device__ unsigned char  g_mi_ih1[NWEL];
__device__ unsigned char  g_mi_hh1[NWEL];

__device__ float    g_h0[2][HID];          // double-buffered h0
__device__ float    g_h1[HID];             // h1 (single buffer is race-free here)
__device__ float    g_part[NOUT][NCTA];    // transposed partial logits
__device__ unsigned g_bar_count = 0;
__device__ unsigned g_bar_gen   = 0;

// ---------------- grid barrier ----------------
__device__ __forceinline__ void grid_barrier() {
    __syncthreads();
    if (threadIdx.x == 0) {
        __threadfence();
        unsigned g = *((volatile unsigned*)&g_bar_gen);
        unsigned arrived = atomicAdd(&g_bar_count, 1u);
        if (arrived == NCTA - 1) {
            atomicExch(&g_bar_count, 0u);
            __threadfence();
            atomicExch(&g_bar_gen, g + 1u);
        } else {
            while (*((volatile unsigned*)&g_bar_gen) == g) { }
        }
        __threadfence();
    }
    __syncthreads();
}

// ---------------- JAX threefry2x32 ----------------
__device__ __forceinline__ void tf_round(uint32_t& x0, uint32_t& x1, int r) {
    x0 += x1;
    x1 = (x1 << r) | (x1 >> (32 - r));
    x1 ^= x0;
}
__device__ __forceinline__ uint2 threefry2x32(uint32_t k0, uint32_t k1,
                                              uint32_t x0, uint32_t x1) {
    uint32_t ks2 = k0 ^ k1 ^ 0x1BD11BDAu;
    x0 += k0; x1 += k1;
    tf_round(x0,x1,13); tf_round(x0,x1,15); tf_round(x0,x1,26); tf_round(x0,x1,6);
    x0 += k1; x1 += ks2 + 1u;
    tf_round(x0,x1,17); tf_round(x0,x1,29); tf_round(x0,x1,16); tf_round(x0,x1,24);
    x0 += ks2; x1 += k0 + 2u;
    tf_round(x0,x1,13); tf_round(x0,x1,15); tf_round(x0,x1,26); tf_round(x0,x1,6);
    x0 += k0; x1 += k1 + 3u;
    tf_round(x0,x1,17); tf_round(x0,x1,29); tf_round(x0,x1,16); tf_round(x0,x1,24);
    x0 += k1; x1 += ks2 + 4u;
    tf_round(x0,x1,13); tf_round(x0,x1,15); tf_round(x0,x1,26); tf_round(x0,x1,6);
    x0 += ks2; x1 += k0 + 5u;
    return make_uint2(x0, x1);
}

__device__ __forceinline__ float sigf(float x) { return 1.0f / (1.0f + expf(-x)); }

// reconstruct fp32 from hi-ushort + mid-byte via PRMT (low byte = junk, < 2^-16 rel)
__device__ __forceinline__ float prmtf(uint32_t a, uint32_t b, uint32_t s) {
    uint32_t r;
    asm("prmt.b32 %0,%1,%2,%3;" : "=r"(r) : "r"(a), "r"(b), "r"(s));
    return __uint_as_float(r);
}

// dot of 8 consecutive compressed weights with 8 floats (x0,x1)
__device__ __forceinline__ float dot8(const unsigned short* __restrict__ hp,
                                      const unsigned char*  __restrict__ mp,
                                      float4 x0, float4 x1, float acc) {
    uint4 H = __ldcg((const uint4*)hp);   // 8 ushorts
    uint2 M = __ldcg((const uint2*)mp);   // 8 bytes
    acc = fmaf(prmtf(H.x, M.x, 0x1044u), x0.x, acc);
    acc = fmaf(prmtf(H.x, M.x, 0x3255u), x0.y, acc);
    acc = fmaf(prmtf(H.y, M.x, 0x1066u), x0.z, acc);
    acc = fmaf(prmtf(H.y, M.x, 0x3277u), x0.w, acc);
    acc = fmaf(prmtf(H.z, M.y, 0x1044u), x1.x, acc);
    acc = fmaf(prmtf(H.z, M.y, 0x3255u), x1.y, acc);
    acc = fmaf(prmtf(H.w, M.y, 0x1066u), x1.z, acc);
    acc = fmaf(prmtf(H.w, M.y, 0x3277u), x1.w, acc);
    return acc;
}

// ---------------- conversion kernel (runs every launch; deterministic) ----------------
__global__ void conv_kernel(const float* __restrict__ whh0,
                            const float* __restrict__ wih1,
                            const float* __restrict__ whh1) {
    for (int i = blockIdx.x * blockDim.x + threadIdx.x; i < NWEL;
         i += gridDim.x * blockDim.x) {
        uint32_t u;
        u = __float_as_uint(whh0[i]) + 0x80u;
        g_hi_hh0[i] = (unsigned short)(u >> 16); g_mi_hh0[i] = (unsigned char)(u >> 8);
        u = __float_as_uint(wih1[i]) + 0x80u;
        g_hi_ih1[i] = (unsigned short)(u >> 16); g_mi_ih1[i] = (unsigned char)(u >> 8);
        u = __float_as_uint(whh1[i]) + 0x80u;
        g_hi_hh1[i] = (unsigned short)(u >> 16); g_mi_hh1[i] = (unsigned char)(u >> 8);
    }
}

// ---------------- main persistent kernel ----------------
__global__ void __launch_bounds__(TPB, 1)
lstm_autoreg_kernel(const float* __restrict__ inputs,
                    const float* __restrict__ h_init,
                    const float* __restrict__ c_init,
                    const float* __restrict__ W_ih0,
                    const float* __restrict__ b_ih0,
                    const float* __restrict__ b_hh0,
                    const float* __restrict__ b_ih1,
                    const float* __restrict__ b_hh1,
                    const float* __restrict__ W_lin,
                    const float* __restrict__ b_lin,
                    const float* __restrict__ lookup,
                    float* __restrict__ out)
{
    __shared__ float s_hA[HID];
    __shared__ float s_hB[HID];
    __shared__ float s_Wih0[RPC][INSZ];
    __shared__ float s_bias0[RPC];
    __shared__ float s_bias1[RPC];
    __shared__ float s_gih0[RPC];
    __shared__ float s_g[RPC];      // dot results (reused R1/R2)
    __shared__ float s_d3[RPC];     // W_hh1 . h1 dot, carried R1 -> R2
    __shared__ float s_c0[UPC], s_c1[UPC];
    __shared__ float s_h1loc[UPC];
    __shared__ float s_x[INSZ];
    __shared__ float s_Wlin[NOUT][UPC];
    __shared__ float s_lookup[NOUT];
    __shared__ float s_blin[NOUT];

    const int tid  = threadIdx.x;
    const int cta  = blockIdx.x;
    const int u0   = cta * UPC;
    const int warp = tid >> 5;
    const int lane = tid & 31;
    const float neginf = __int_as_float(0xff800000);

    // ---------------- one-time init ----------------
    for (int r = tid; r < RPC; r += TPB) {
        int t = r / UPC, ul = r - t * UPC;
        int grow = t * HID + u0 + ul;
        s_bias0[r] = b_ih0[grow] + b_hh0[grow];
        s_bias1[r] = b_ih1[grow] + b_hh1[grow];
    }
    for (int idx = tid; idx < RPC * INSZ; idx += TPB) {
        int r = idx >> 5, k = idx & 31;
        int t = r / UPC, ul = r - t * UPC;
        s_Wih0[r][k] = W_ih0[(t * HID + u0 + ul) * INSZ + k];
    }
    for (int idx = tid; idx < NOUT * UPC; idx += TPB) {
        int o = idx / UPC, ul = idx - o * UPC;
        s_Wlin[o][ul] = W_lin[o * HID + u0 + ul];
    }
    if (tid < NOUT) { s_lookup[tid] = lookup[tid]; s_blin[tid] = b_lin[tid]; }
    if (tid < UPC) {
        s_c0[tid] = c_init[u0 + tid];
        s_c1[tid] = c_init[HID + u0 + tid];
        g_h0[0][u0 + tid] = h_init[u0 + tid];
        g_h1[u0 + tid]    = h_init[HID + u0 + tid];
    }
    grid_barrier();

    // local row ids and global weight row offsets for this warp
    const int r0 = warp * RPW;
    const int r1 = r0 + 1;
    const size_t o0 = (size_t)((r0 / UPC) * HID + u0 + (r0 % UPC)) * HID;
    const size_t o1 = (size_t)((r1 / UPC) * HID + u0 + (r1 % UPC)) * HID;

    int p = 0;
    for (int s = 0; s < STOT; ++s) {
        // ---- R1: stage h0(s-1), h1(s-1) ----
        {
            const float4* sA = (const float4*)(&g_h0[p][0]);
            const float4* sB = (const float4*)g_h1;
            float4* dA = (float4*)s_hA;
            float4* dB = (float4*)s_hB;
            for (int q = tid; q < HV4; q += TPB) { dA[q] = sA[q]; dB[q] = sB[q]; }
        }
        __syncthreads();

        // ---- control (warp 0): sample step s-1, update x / gih0 ----
        if (warp == 0) {
            const int sp = s - 1;
            if (sp >= 0) {
                float logit = neginf;
                #pragma unroll
                for (int o = 0; o < NOUT; ++o) {
                    float v = g_part[o][lane] + g_part[o][lane + 32]
                            + g_part[o][lane + 64] + g_part[o][lane + 96];
                    #pragma unroll
                    for (int off = 16; off; off >>= 1)
                        v += __shfl_xor_sync(0xffffffffu, v, off);
                    if (lane == o) logit = v + s_blin[o];
                }
                // gumbel sample
                uint2 key = threefry2x32(0u, 42u, 0u, (uint32_t)sp);
                float v = neginf;
                if (lane < NOUT) {
                    uint2 bb = threefry2x32(key.x, key.y, 0u, (uint32_t)lane);
                    uint32_t bits = bb.x ^ bb.y;
                    float f = __uint_as_float((bits >> 9) | 0x3F800000u) - 1.0f;
                    float u = fmaxf(f + 1.17549435e-38f, 1.17549435e-38f);
                    v = logit - logf(-logf(u));
                }
                int aidx = lane;
                #pragma unroll
                for (int off = 16; off; off >>= 1) {
                    float ov = __shfl_xor_sync(0xffffffffu, v, off);
                    int   oi = __shfl_xor_sync(0xffffffffu, aidx, off);
                    if (ov > v || (ov == v && oi < aidx)) { v = ov; aidx = oi; }
                }
                float m = (lane < NOUT) ? logit : neginf;
                #pragma unroll
                for (int off = 16; off; off >>= 1)
                    m = fmaxf(m, __shfl_xor_sync(0xffffffffu, m, off));
                float e = (lane < NOUT) ? expf(logit - m) : 0.f;
                float sum = e;
                #pragma unroll
                for (int off = 16; off; off >>= 1)
                    sum += __shfl_xor_sync(0xffffffffu, sum, off);

                const int jp = sp & 31;
                if (jp != 0) {
                    float sc = s_lookup[aidx];
                    float xj = s_x[jp];
                    float d  = (sc - 1.0f) * xj;
                    #pragma unroll
                    for (int r = lane; r < RPC; r += 32)
                        s_gih0[r] = fmaf(d, s_Wih0[r][jp], s_gih0[r]);
                    if (lane == 0) s_x[jp] = xj * sc;
                }
                if (cta == 0) {
                    if (lane == 0) out[sp] = (float)aidx;
                    if (lane < NOUT) out[STOT + sp * NOUT + lane] = e / sum;
                }
            }
            // fresh input at start of each timestep
            if ((s & 31) == 0) {
                s_x[lane] = inputs[(s >> 5) * INSZ + lane];
                __syncwarp();
                for (int r = lane; r < RPC; r += 32) {
                    float acc = s_bias0[r];
                    #pragma unroll
                    for (int k = 0; k < INSZ; ++k)
                        acc = fmaf(s_x[k], s_Wih0[r][k], acc);
                    s_gih0[r] = acc;
                }
            }
        }

        // ---- R1 dots: d1 = Whh0 . h0(s-1), d3 = Whh1 . h1(s-1) ----
        {
            const float4* sA4 = (const float4*)s_hA;
            const float4* sB4 = (const float4*)s_hB;
            float a0 = 0.f, a1 = 0.f, b0 = 0.f, b1 = 0.f;
            #pragma unroll 2
            for (int it = 0; it < 6; ++it) {
                const int e  = it * 256 + lane * 8;
                const int e4 = e >> 2;
                float4 xA0 = sA4[e4], xA1 = sA4[e4 + 1];
                float4 xB0 = sB4[e4], xB1 = sB4[e4 + 1];
                a0 = dot8(g_hi_hh0 + o0 + e, g_mi_hh0 + o0 + e, xA0, xA1, a0);
                a1 = dot8(g_hi_hh0 + o1 + e, g_mi_hh0 + o1 + e, xA0, xA1, a1);
                b0 = dot8(g_hi_hh1 + o0 + e, g_mi_hh1 + o0 + e, xB0, xB1, b0);
                b1 = dot8(g_hi_hh1 + o1 + e, g_mi_hh1 + o1 + e, xB0, xB1, b1);
            }
            #pragma unroll
            for (int off = 16; off; off >>= 1) {
                a0 += __shfl_xor_sync(0xffffffffu, a0, off);
                a1 += __shfl_xor_sync(0xffffffffu, a1, off);
                b0 += __shfl_xor_sync(0xffffffffu, b0, off);
                b1 += __shfl_xor_sync(0xffffffffu, b1, off);
            }
            if (lane == 0) {
                s_g[r0] = a0; s_g[r1] = a1;
                s_d3[r0] = b0; s_d3[r1] = b1;
            }
        }
        __syncthreads();

        // ---- layer-0 cell ----
        if (tid < UPC) {
            float gi = s_g[tid]           + s_gih0[tid];
            float gf = s_g[UPC + tid]     + s_gih0[UPC + tid];
            float gg = s_g[2 * UPC + tid] + s_gih0[2 * UPC + tid];
            float go = s_g[3 * UPC + tid] + s_gih0[3 * UPC + tid];
            float c2 = sigf(gf) * s_c0[tid] + sigf(gi) * tanhf(gg);
            float h2 = sigf(go) * tanhf(c2);
            s_c0[tid] = c2;
            g_h0[p ^ 1][u0 + tid] = h2;
        }
        grid_barrier();

        // ---- R2: stage h0(s), dot d2 = Wih1 . h0(s) ----
        {
            const float4* sA = (const float4*)(&g_h0[p ^ 1][0]);
            float4* dA = (float4*)s_hA;
            for (int q = tid; q < HV4; q += TPB) dA[q] = sA[q];
        }
        __syncthreads();
        {
            const float4* sA4 = (const float4*)s_hA;
            float c0a = 0.f, c1a = 0.f;
            #pragma unroll 3
            for (int it = 0; it < 6; ++it) {
                const int e  = it * 256 + lane * 8;
                const int e4 = e >> 2;
                float4 xA0 = sA4[e4], xA1 = sA4[e4 + 1];
                c0a = dot8(g_hi_ih1 + o0 + e, g_mi_ih1 + o0 + e, xA0, xA1, c0a);
                c1a = dot8(g_hi_ih1 + o1 + e, g_mi_ih1 + o1 + e, xA0, xA1, c1a);
            }
            #pragma unroll
            for (int off = 16; off; off >>= 1) {
                c0a += __shfl_xor_sync(0xffffffffu, c0a, off);
                c1a += __shfl_xor_sync(0xffffffffu, c1a, off);
            }
            if (lane == 0) { s_g[r0] = c0a; s_g[r1] = c1a; }
        }
        __syncthreads();

        // ---- layer-1 cell + partial logits ----
        if (tid < UPC) {
            float gi = s_g[tid]           + s_d3[tid]           + s_bias1[tid];
            float gf = s_g[UPC + tid]     + s_d3[UPC + tid]     + s_bias1[UPC + tid];
            float gg = s_g[2 * UPC + tid] + s_d3[2 * UPC + tid] + s_bias1[2 * UPC + tid];
            float go = s_g[3 * UPC + tid] + s_d3[3 * UPC + tid] + s_bias1[3 * UPC + tid];
            float c2 = sigf(gf) * s_c1[tid] + sigf(gi) * tanhf(gg);
            float h2 = sigf(go) * tanhf(c2);
            s_c1[tid] = c2;
            s_h1loc[tid] = h2;
            g_h1[u0 + tid] = h2;
        }
        __syncthreads();
        if (tid < NOUT) {
            float acc = 0.f;
            #pragma unroll
            for (int ul = 0; ul < UPC; ++ul)
                acc = fmaf(s_h1loc[ul], s_Wlin[tid][ul], acc);
            g_part[tid][cta] = acc;
        }
        grid_barrier();
        p ^= 1;
    }

    // ---- epilogue: sample the final step (cta 0 only) ----
    if (cta == 0 && warp == 0) {
        const int sp = STOT - 1;
        float logit = neginf;
        #pragma unroll
        for (int o = 0; o < NOUT; ++o) {
            float v = g_part[o][lane] + g_part[o][lane + 32]
                    + g_part[o][lane + 64] + g_part[o][lane + 96];
            #pragma unroll
            for (int off = 16; off; off >>= 1)
                v += __shfl_xor_sync(0xffffffffu, v, off);
            if (lane == o) logit = v + s_blin[o];
        }
        uint2 key = threefry2x32(0u, 42u, 0u, (uint32_t)sp);
        float v = neginf;
        if (lane < NOUT) {
            uint2 bb = threefry2x32(key.x, key.y, 0u, (uint32_t)lane);
            uint32_t bits = bb.x ^ bb.y;
            float f = __uint_as_float((bits >> 9) | 0x3F800000u) - 1.0f;
            float u = fmaxf(f + 1.17549435e-38f, 1.17549435e-38f);
            v = logit - logf(-logf(u));
        }
        int aidx = lane;
        #pragma unroll
        for (int off = 16; off; off >>= 1) {
            float ov = __shfl_xor_sync(0xffffffffu, v, off);
            int   oi = __shfl_xor_sync(0xffffffffu, aidx, off);
            if (ov > v || (ov == v && oi < aidx)) { v = ov; aidx = oi; }
        }
        float m = (lane < NOUT) ? logit : neginf;
        #pragma unroll
        for (int off = 16; off; off >>= 1)
            m = fmaxf(m, __shfl_xor_sync(0xffffffffu, m, off));
        float e = (lane < NOUT) ? expf(logit - m) : 0.f;
        float sum = e;
        #pragma unroll
        for (int off = 16; off; off >>= 1)
            sum += __shfl_xor_sync(0xffffffffu, sum, off);
        if (lane == 0) out[sp] = (float)aidx;
        if (lane < NOUT) out[STOT + sp * NOUT + lane] = e / sum;
    }
}

extern "C" void kernel_launch(void* const* d_in, const int* in_sizes, int n_in,
                              void* d_out, int out_size) {
    (void)in_sizes; (void)n_in; (void)out_size;
    conv_kernel<<<4608, 1024>>>(
        (const float*)d_in[4],   // W_hh0
        (const float*)d_in[7],   // W_ih1
        (const float*)d_in[8]);  // W_hh1
    lstm_autoreg_kernel<<<NCTA, TPB>>>(
        (const float*)d_in[0],   // inputs
        (const float*)d_in[1],   // h_init
        (const float*)d_in[2],   // c_init
        (const float*)d_in[3],   // W_ih0
        (const float*)d_in[5],   // b_ih0
        (const float*)d_in[6],   // b_hh0
        (const float*)d_in[9],   // b_ih1
        (const float*)d_in[10],  // b_hh1
        (const float*)d_in[11],  // W_lin
        (const float*)d_in[12],  // b_lin
        (const float*)d_in[13],  // lookup
        (float*)d_out);
}

// round 3
// speedup vs baseline: 1.7193x; 1.2447x over previous
#include <cuda_runtime.h>
#include <math.h>
#include <stdint.h>

// ---------------- problem constants ----------------
#define NCTA  128
#define TPB   768
#define NWARP (TPB / 32)      // 24
#define HID   1536
#define INSZ  32
#define NOUT  10
#define STOT  2048            // T * INPUT_SIZE
#define UPC   (HID / NCTA)    // 12 hidden units per CTA
#define RPC   (4 * UPC)       // 48 gate rows per CTA
#define HV4   (HID / 4)       // 384 float4 per hidden vector
#define NWEL  (4 * HID * HID) // elements per big matrix

// ---------------- persistent device state ----------------
__device__ unsigned short g_hi_hh0[NWEL];
__device__ unsigned short g_hi_ih1[NWEL];
__device__ unsigned short g_hi_hh1[NWEL];
__device__ unsigned char  g_mi_hh0[NWEL];
__device__ unsigned char  g_mi_ih1[NWEL];
__device__ unsigned char  g_mi_hh1[NWEL];

__device__ float    g_h0[2][HID];
__device__ float    g_h1[HID];
__device__ float    g_logits[2][NOUT];   // atomically accumulated logits
__device__ uint2    g_keys[STOT];        // precomputed threefry step keys
__device__ unsigned g_bar_count = 0;
__device__ unsigned g_bar_gen   = 0;

// ---------------- grid barrier ----------------
__device__ __forceinline__ void grid_barrier() {
    __syncthreads();
    if (threadIdx.x == 0) {
        __threadfence();
        unsigned g = *((volatile unsigned*)&g_bar_gen);
        unsigned arrived = atomicAdd(&g_bar_count, 1u);
        if (arrived == NCTA - 1) {
            atomicExch(&g_bar_count, 0u);
            __threadfence();
            atomicExch(&g_bar_gen, g + 1u);
        } else {
            while (*((volatile unsigned*)&g_bar_gen) == g) { }
        }
        __threadfence();
    }
    __syncthreads();
}

// ---------------- JAX threefry2x32 ----------------
__device__ __forceinline__ void tf_round(uint32_t& x0, uint32_t& x1, int r) {
    x0 += x1;
    x1 = (x1 << r) | (x1 >> (32 - r));
    x1 ^= x0;
}
__device__ __forceinline__ uint2 threefry2x32(uint32_t k0, uint32_t k1,
                                              uint32_t x0, uint32_t x1) {
    uint32_t ks2 = k0 ^ k1 ^ 0x1BD11BDAu;
    x0 += k0; x1 += k1;
    tf_round(x0,x1,13); tf_round(x0,x1,15); tf_round(x0,x1,26); tf_round(x0,x1,6);
    x0 += k1; x1 += ks2 + 1u;
    tf_round(x0,x1,17); tf_round(x0,x1,29); tf_round(x0,x1,16); tf_round(x0,x1,24);
    x0 += ks2; x1 += k0 + 2u;
    tf_round(x0,x1,13); tf_round(x0,x1,15); tf_round(x0,x1,26); tf_round(x0,x1,6);
    x0 += k0; x1 += k1 + 3u;
    tf_round(x0,x1,17); tf_round(x0,x1,29); tf_round(x0,x1,16); tf_round(x0,x1,24);
    x0 += k1; x1 += ks2 + 4u;
    tf_round(x0,x1,13); tf_round(x0,x1,15); tf_round(x0,x1,26); tf_round(x0,x1,6);
    x0 += ks2; x1 += k0 + 5u;
    return make_uint2(x0, x1);
}

__device__ __forceinline__ float sigf(float x) { return 1.0f / (1.0f + expf(-x)); }

__device__ __forceinline__ float prmtf(uint32_t a, uint32_t b, uint32_t s) {
    uint32_t r;
    asm("prmt.b32 %0,%1,%2,%3;" : "=r"(r) : "r"(a), "r"(b), "r"(s));
    return __uint_as_float(r);
}

// 8 weights (preloaded H,M) dotted with 8 floats
__device__ __forceinline__ float fma8(uint4 H, uint2 M, float4 x0, float4 x1, float acc) {
    acc = fmaf(prmtf(H.x, M.x, 0x1044u), x0.x, acc);
    acc = fmaf(prmtf(H.x, M.x, 0x3255u), x0.y, acc);
    acc = fmaf(prmtf(H.y, M.x, 0x1066u), x0.z, acc);
    acc = fmaf(prmtf(H.y, M.x, 0x3277u), x0.w, acc);
    acc = fmaf(prmtf(H.z, M.y, 0x1044u), x1.x, acc);
    acc = fmaf(prmtf(H.z, M.y, 0x3255u), x1.y, acc);
    acc = fmaf(prmtf(H.w, M.y, 0x1066u), x1.z, acc);
    acc = fmaf(prmtf(H.w, M.y, 0x3277u), x1.w, acc);
    return acc;
}

// group dot: 4 consecutive rows, one half, one source vector.
// rowb = element offset of (row0, this half, this lane); writes s_d[(rloc+i)*2+half]
__device__ __forceinline__ void dot_group(const unsigned short* __restrict__ hi,
                                          const unsigned char*  __restrict__ mi,
                                          size_t rowb,
                                          const float4* __restrict__ sh4,
                                          int xbase, int lane, int half, int rloc,
                                          float* __restrict__ s_d) {
    float a0 = 0.f, a1 = 0.f, a2 = 0.f, a3 = 0.f;
    #pragma unroll
    for (int c = 0; c < 3; ++c) {
        const size_t o = rowb + (size_t)c * 256;
        uint4 H0 = __ldcg((const uint4*)(hi + o));
        uint4 H1 = __ldcg((const uint4*)(hi + o + HID));
        uint4 H2 = __ldcg((const uint4*)(hi + o + 2 * HID));
        uint4 H3 = __ldcg((const uint4*)(hi + o + 3 * HID));
        uint2 M0 = __ldcg((const uint2*)(mi + o));
        uint2 M1 = __ldcg((const uint2*)(mi + o + HID));
        uint2 M2 = __ldcg((const uint2*)(mi + o + 2 * HID));
        uint2 M3 = __ldcg((const uint2*)(mi + o + 3 * HID));
        float4 x0 = sh4[xbase + c * 64];
        float4 x1 = sh4[xbase + c * 64 + 1];
        a0 = fma8(H0, M0, x0, x1, a0);
        a1 = fma8(H1, M1, x0, x1, a1);
        a2 = fma8(H2, M2, x0, x1, a2);
        a3 = fma8(H3, M3, x0, x1, a3);
    }
    #pragma unroll
    for (int off = 16; off; off >>= 1) {
        a0 += __shfl_xor_sync(0xffffffffu, a0, off);
        a1 += __shfl_xor_sync(0xffffffffu, a1, off);
        a2 += __shfl_xor_sync(0xffffffffu, a2, off);
        a3 += __shfl_xor_sync(0xffffffffu, a3, off);
    }
    if (lane == 0) {
        s_d[(rloc    ) * 2 + half] = a0;
        s_d[(rloc + 1) * 2 + half] = a1;
        s_d[(rloc + 2) * 2 + half] = a2;
        s_d[(rloc + 3) * 2 + half] = a3;
    }
}

// ---------------- conversion kernel ----------------
__global__ void conv_kernel(const float* __restrict__ whh0,
                            const float* __restrict__ wih1,
                            const float* __restrict__ whh1) {
    int gid = blockIdx.x * blockDim.x + threadIdx.x;
    for (int i = gid; i < NWEL; i += gridDim.x * blockDim.x) {
        uint32_t u;
        u = __float_as_uint(whh0[i]) + 0x80u;
        g_hi_hh0[i] = (unsigned short)(u >> 16); g_mi_hh0[i] = (unsigned char)(u >> 8);
        u = __float_as_uint(wih1[i]) + 0x80u;
        g_hi_ih1[i] = (unsigned short)(u >> 16); g_mi_ih1[i] = (unsigned char)(u >> 8);
        u = __float_as_uint(whh1[i]) + 0x80u;
        g_hi_hh1[i] = (unsigned short)(u >> 16); g_mi_hh1[i] = (unsigned char)(u >> 8);
    }
    if (gid < STOT) g_keys[gid] = threefry2x32(0u, 42u, 0u, (uint32_t)gid);
}

// ---------------- main persistent kernel ----------------
__global__ void __launch_bounds__(TPB, 1)
lstm_autoreg_kernel(const float* __restrict__ inputs,
                    const float* __restrict__ h_init,
                    const float* __restrict__ c_init,
                    const float* __restrict__ W_ih0,
                    const float* __restrict__ b_ih0,
                    const float* __restrict__ b_hh0,
                    const float* __restrict__ b_ih1,
                    const float* __restrict__ b_hh1,
                    const float* __restrict__ W_lin,
                    const float* __restrict__ b_lin,
                    const float* __restrict__ lookup,
                    float* __restrict__ out)
{
    __shared__ float s_hA[HID];
    __shared__ float s_hB[HID];
    __shared__ float s_Wih0[RPC][INSZ];
    __shared__ float s_bias0[RPC];
    __shared__ float s_bias1[RPC];
    __shared__ float s_gih0[RPC];
    __shared__ float s_d1[RPC * 2];   // hh0 . h0(s-1), per (row,half)
    __shared__ float s_d3[RPC * 2];   // hh1 . h1(s-1)
    __shared__ float s_d2[RPC * 2];   // ih1 . h0(s)
    __shared__ float s_c0[UPC], s_c1[UPC];
    __shared__ float s_h1loc[UPC];
    __shared__ float s_x[INSZ];
    __shared__ float s_Wlin[NOUT][UPC];
    __shared__ float s_lookup[NOUT];
    __shared__ float s_blin[NOUT];

    const int tid  = threadIdx.x;
    const int cta  = blockIdx.x;
    const int u0   = cta * UPC;
    const int warp = tid >> 5;
    const int lane = tid & 31;
    const float neginf = __int_as_float(0xff800000);

    // warp task geometry: 4 consecutive local rows, one half
    const int half = warp & 1;
    const int rloc = (warp >> 1) * 4;                 // 0..44, never straddles a gate
    const size_t grow = (size_t)((rloc / UPC) * HID + u0 + (rloc % UPC));
    const size_t rowb = grow * HID + half * 768 + lane * 8;
    const int xbase = half * 192 + lane * 2;

    // ---------------- one-time init ----------------
    for (int r = tid; r < RPC; r += TPB) {
        int t = r / UPC, ul = r - t * UPC;
        int g = t * HID + u0 + ul;
        s_bias0[r] = b_ih0[g] + b_hh0[g];
        s_bias1[r] = b_ih1[g] + b_hh1[g];
    }
    for (int idx = tid; idx < RPC * INSZ; idx += TPB) {
        int r = idx >> 5, k = idx & 31;
        int t = r / UPC, ul = r - t * UPC;
        s_Wih0[r][k] = W_ih0[(t * HID + u0 + ul) * INSZ + k];
    }
    for (int idx = tid; idx < NOUT * UPC; idx += TPB) {
        int o = idx / UPC, ul = idx - o * UPC;
        s_Wlin[o][ul] = W_lin[o * HID + u0 + ul];
    }
    if (tid < NOUT) { s_lookup[tid] = lookup[tid]; s_blin[tid] = b_lin[tid]; }
    if (tid < UPC) {
        s_c0[tid] = c_init[u0 + tid];
        s_c1[tid] = c_init[HID + u0 + tid];
        g_h0[0][u0 + tid] = h_init[u0 + tid];
        g_h1[u0 + tid]    = h_init[HID + u0 + tid];
    }
    if (cta == 0 && tid < 2 * NOUT) ((float*)g_logits)[tid] = 0.f;
    grid_barrier();

    int p = 0;
    for (int s = 0; s < STOT; ++s) {
        // ---- stage h0(s-1), h1(s-1) ----
        {
            const float4* sA = (const float4*)(&g_h0[p][0]);
            const float4* sB = (const float4*)g_h1;
            float4* dA = (float4*)s_hA;
            float4* dB = (float4*)s_hB;
            for (int q = tid; q < HV4; q += TPB) { dA[q] = sA[q]; dB[q] = sB[q]; }
        }
        __syncthreads();

        // ---- control (warp 0): sample step s-1, update x / gih0 ----
        if (warp == 0) {
            const int sp = s - 1;
            if (sp >= 0) {
                float logit = neginf;
                if (lane < NOUT) logit = __ldcg(&g_logits[sp & 1][lane]) + s_blin[lane];
                uint2 key = g_keys[sp];
                float v = neginf;
                if (lane < NOUT) {
                    uint2 bb = threefry2x32(key.x, key.y, 0u, (uint32_t)lane);
                    uint32_t bits = bb.x ^ bb.y;
                    float f = __uint_as_float((bits >> 9) | 0x3F800000u) - 1.0f;
                    float u = fmaxf(f + 1.17549435e-38f, 1.17549435e-38f);
                    v = logit - logf(-logf(u));
                }
                int aidx = lane;
                #pragma unroll
                for (int off = 16; off; off >>= 1) {
                    float ov = __shfl_xor_sync(0xffffffffu, v, off);
                    int   oi = __shfl_xor_sync(0xffffffffu, aidx, off);
                    if (ov > v || (ov == v && oi < aidx)) { v = ov; aidx = oi; }
                }
                float m = (lane < NOUT) ? logit : neginf;
                #pragma unroll
                for (int off = 16; off; off >>= 1)
                    m = fmaxf(m, __shfl_xor_sync(0xffffffffu, m, off));
                float e = (lane < NOUT) ? expf(logit - m) : 0.f;
                float sum = e;
                #pragma unroll
                for (int off = 16; off; off >>= 1)
                    sum += __shfl_xor_sync(0xffffffffu, sum, off);

                const int jp = sp & 31;
                if (jp != 0) {
                    float sc = s_lookup[aidx];
                    float xj = s_x[jp];
                    float d  = (sc - 1.0f) * xj;
                    #pragma unroll
                    for (int r = lane; r < RPC; r += 32)
                        s_gih0[r] = fmaf(d, s_Wih0[r][jp], s_gih0[r]);
                    if (lane == 0) s_x[jp] = xj * sc;
                }
                if (cta == 0) {
                    if (lane == 0) out[sp] = (float)aidx;
                    if (lane < NOUT) out[STOT + sp * NOUT + lane] = e / sum;
                }
            }
            if ((s & 31) == 0) {
                s_x[lane] = inputs[(s >> 5) * INSZ + lane];
                __syncwarp();
                for (int r = lane; r < RPC; r += 32) {
                    float acc = s_bias0[r];
                    #pragma unroll
                    for (int k = 0; k < INSZ; ++k)
                        acc = fmaf(s_x[k], s_Wih0[r][k], acc);
                    s_gih0[r] = acc;
                }
            }
        }

        // ---- R1 dots: hh0 . h0(s-1) and hh1 . h1(s-1) ----
        dot_group(g_hi_hh0, g_mi_hh0, rowb, (const float4*)s_hA, xbase, lane, half, rloc, s_d1);
        dot_group(g_hi_hh1, g_mi_hh1, rowb, (const float4*)s_hB, xbase, lane, half, rloc, s_d3);
        __syncthreads();

        // ---- layer-0 cell ----
        if (tid < UPC) {
            int r0 = tid, r1 = UPC + tid, r2 = 2 * UPC + tid, r3 = 3 * UPC + tid;
            float gi = s_d1[r0*2] + s_d1[r0*2+1] + s_gih0[r0];
            float gf = s_d1[r1*2] + s_d1[r1*2+1] + s_gih0[r1];
            float gg = s_d1[r2*2] + s_d1[r2*2+1] + s_gih0[r2];
            float go = s_d1[r3*2] + s_d1[r3*2+1] + s_gih0[r3];
            float c2 = sigf(gf) * s_c0[tid] + sigf(gi) * tanhf(gg);
            float h2 = sigf(go) * tanhf(c2);
            s_c0[tid] = c2;
            g_h0[p ^ 1][u0 + tid] = h2;
        }
        grid_barrier();

        // reset the logits buffer consumed this step (safe: all CTAs past control)
        if (cta == 0 && tid < NOUT) g_logits[(s + 1) & 1][tid] = 0.f;

        // ---- R2: stage h0(s), dot ih1 . h0(s) ----
        {
            const float4* sA = (const float4*)(&g_h0[p ^ 1][0]);
            float4* dA = (float4*)s_hA;
            for (int q = tid; q < HV4; q += TPB) dA[q] = sA[q];
        }
        __syncthreads();
        dot_group(g_hi_ih1, g_mi_ih1, rowb, (const float4*)s_hA, xbase, lane, half, rloc, s_d2);
        __syncthreads();

        // ---- layer-1 cell ----
        if (tid < UPC) {
            int r0 = tid, r1 = UPC + tid, r2 = 2 * UPC + tid, r3 = 3 * UPC + tid;
            float gi = s_d2[r0*2] + s_d2[r0*2+1] + s_d3[r0*2] + s_d3[r0*2+1] + s_bias1[r0];
            float gf = s_d2[r1*2] + s_d2[r1*2+1] + s_d3[r1*2] + s_d3[r1*2+1] + s_bias1[r1];
            float gg = s_d2[r2*2] + s_d2[r2*2+1] + s_d3[r2*2] + s_d3[r2*2+1] + s_bias1[r2];
            float go = s_d2[r3*2] + s_d2[r3*2+1] + s_d3[r3*2] + s_d3[r3*2+1] + s_bias1[r3];
            float c2 = sigf(gf) * s_c1[tid] + sigf(gi) * tanhf(gg);
            float h2 = sigf(go) * tanhf(c2);
            s_c1[tid] = c2;
            s_h1loc[tid] = h2;
            g_h1[u0 + tid] = h2;
        }
        __syncthreads();
        if (tid < NOUT) {
            float acc = 0.f;
            #pragma unroll
            for (int ul = 0; ul < UPC; ++ul)
                acc = fmaf(s_h1loc[ul], s_Wlin[tid][ul], acc);
            atomicAdd(&g_logits[s & 1][tid], acc);
        }
        grid_barrier();
        p ^= 1;
    }

    // ---- epilogue: sample the final step (cta 0 only) ----
    if (cta == 0 && warp == 0) {
        const int sp = STOT - 1;
        float logit = neginf;
        if (lane < NOUT) logit = __ldcg(&g_logits[sp & 1][lane]) + s_blin[lane];
        uint2 key = g_keys[sp];
        float v = neginf;
        if (lane < NOUT) {
            uint2 bb = threefry2x32(key.x, key.y, 0u, (uint32_t)lane);
            uint32_t bits = bb.x ^ bb.y;
            float f = __uint_as_float((bits >> 9) | 0x3F800000u) - 1.0f;
            float u = fmaxf(f + 1.17549435e-38f, 1.17549435e-38f);
            v = logit - logf(-logf(u));
        }
        int aidx = lane;
        #pragma unroll
        for (int off = 16; off; off >>= 1) {
            float ov = __shfl_xor_sync(0xffffffffu, v, off);
            int   oi = __shfl_xor_sync(0xffffffffu, aidx, off);
            if (ov > v || (ov == v && oi < aidx)) { v = ov; aidx = oi; }
        }
        float m = (lane < NOUT) ? logit : neginf;
        #pragma unroll
        for (int off = 16; off; off >>= 1)
            m = fmaxf(m, __shfl_xor_sync(0xffffffffu, m, off));
        float e = (lane < NOUT) ? expf(logit - m) : 0.f;
        float sum = e;
        #pragma unroll
        for (int off = 16; off; off >>= 1)
            sum += __shfl_xor_sync(0xffffffffu, sum, off);
        if (lane == 0) out[sp] = (float)aidx;
        if (lane < NOUT) out[STOT + sp * NOUT + lane] = e / sum;
    }
}

extern "C" void kernel_launch(void* const* d_in, const int* in_sizes, int n_in,
                              void* d_out, int out_size) {
    (void)in_sizes; (void)n_in; (void)out_size;
    conv_kernel<<<4608, 1024>>>(
        (const float*)d_in[4],   // W_hh0
        (const float*)d_in[7],   // W_ih1
        (const float*)d_in[8]);  // W_hh1
    lstm_autoreg_kernel<<<NCTA, TPB>>>(
        (const float*)d_in[0],   // inputs
        (const float*)d_in[1],   // h_init
        (const float*)d_in[2],   // c_init
        (const float*)d_in[3],   // W_ih0
        (const float*)d_in[5],   // b_ih0
        (const float*)d_in[6],   // b_hh0
        (const float*)d_in[9],   // b_ih1
        (const float*)d_in[10],  // b_hh1
        (const float*)d_in[11],  // W_lin
        (const float*)d_in[12],  // b_lin
        (const float*)d_in[13],  // lookup
        (float*)d_out);
}